// round 6
// baseline (speedup 1.0000x reference)
#include <cuda_runtime.h>
#include <math.h>

#define NSTACK 12
#define ZEROOFF 0.001f
#define EPSV 1e-8f
#define CREC 52     // per-step coef record: a[0:12] c[12:24] e[24:36] q[36:48] pop[48] pad->52

// Fixed shapes (B=32, T=256, V=2048) for scratch sizing.
__device__ float g_interp[32 * 256];
__device__ float g_partd[32 * 4 * 256];  // per (b, blk, t): partial sp.latch_{t-1}
__device__ float g_partn[32 * 4 * 256];  // per (b, blk, t): partial ||latch_{t-1}||^2
__device__ float g_partsp[4];            // per blk: partial ||sp||^2

__device__ __forceinline__ float dot4(float4 a, float4 b) {
    return a.x * b.x + a.y * b.y + a.z * b.z + a.w * b.w;
}

// ---------------------------------------------------------------------------
// K1: interp[b,t] = cos(latch_enable, x[b,t]).  One WARP per row, MLP=8.
// le-norm computed per-warp (le is loaded anyway) -> no k0 dependency.
// ---------------------------------------------------------------------------
__global__ void k1_interp(const float* __restrict__ x, const float* __restrict__ le, int V) {
    int row = blockIdx.x * 8 + (threadIdx.x >> 5);
    int lane = threadIdx.x & 31;
    const float4* xp = (const float4*)(x + (size_t)row * V);
    const float4* le4 = (const float4*)le;
    float d = 0.f, n = 0.f, m = 0.f;
    for (int i0 = lane; i0 < V / 4; i0 += 128) {
        float4 xv[4], l[4];
        #pragma unroll
        for (int j = 0; j < 4; j++) { xv[j] = xp[i0 + 32 * j]; l[j] = le4[i0 + 32 * j]; }
        #pragma unroll
        for (int j = 0; j < 4; j++) {
            d += dot4(l[j], xv[j]);
            n += dot4(xv[j], xv[j]);
            m += dot4(l[j], l[j]);
        }
    }
    #pragma unroll
    for (int o = 16; o > 0; o >>= 1) {
        d += __shfl_xor_sync(0xffffffffu, d, o);
        n += __shfl_xor_sync(0xffffffffu, n, o);
        m += __shfl_xor_sync(0xffffffffu, m, o);
    }
    if (lane == 0) {
        float nle = fmaxf(sqrtf(m), EPSV);
        float nx = fmaxf(sqrtf(n), EPSV);
        g_interp[row] = d / (nle * nx);
    }
}

// ---------------------------------------------------------------------------
// K2: latch scan + fused pop partials, software-pipelined x loads (ping-pong
// 8-step batches), butterflies hoisted out of the recurrence.
// grid (4, B), block 128. blockIdx.y==0 blocks also emit ||sp||^2 partials.
// ---------------------------------------------------------------------------
__global__ void k2_latch(const float* __restrict__ x, const float* __restrict__ latch0,
                         const float* __restrict__ sp, float* __restrict__ latches,
                         int T, int V) {
    __shared__ float s_i[256];
    __shared__ float s_wd[256][4];
    __shared__ float s_wn[256][4];
    __shared__ float s_sp[4];
    int b = blockIdx.y;
    int tid = threadIdx.x;
    int lane = tid & 31;
    int w = tid >> 5;
    int v4 = blockIdx.x * blockDim.x + tid;
    int stride4 = V >> 2;

    for (int t = tid; t < T; t += blockDim.x) s_i[t] = g_interp[b * T + t];
    __syncthreads();

    float4 sp4 = ((const float4*)sp)[v4];
    float4 latch = ((const float4*)(latch0 + (size_t)b * V))[v4];
    const float4* xp = (const float4*)(x + (size_t)b * T * V) + v4;
    float4* lp = (float4*)(latches + (size_t)b * T * V) + v4;

    // slot 0: stats of latch0 (for pop[0]); also sp-norm partial for b==0.
    {
        float d = dot4(sp4, latch);
        float n = dot4(latch, latch);
        float m = dot4(sp4, sp4);
        #pragma unroll
        for (int o = 16; o > 0; o >>= 1) {
            d += __shfl_xor_sync(0xffffffffu, d, o);
            n += __shfl_xor_sync(0xffffffffu, n, o);
            m += __shfl_xor_sync(0xffffffffu, m, o);
        }
        if (lane == 0) { s_wd[0][w] = d; s_wn[0][w] = n; s_sp[w] = m; }
    }

    float4 xa[8], xb8[8];
    #pragma unroll
    for (int j = 0; j < 8; j++) xa[j] = xp[(size_t)j * stride4];

    for (int t0 = 0; t0 < T; t0 += 16) {
        // batch A covers t0..t0+7 (already in xa); issue loads for t0+8..t0+15
        #pragma unroll
        for (int j = 0; j < 8; j++) xb8[j] = xp[(size_t)(t0 + 8 + j) * stride4];
        float d8[8], n8[8];
        #pragma unroll
        for (int j = 0; j < 8; j++) {
            float i = s_i[t0 + j];
            latch.x = fmaf(i, xa[j].x - latch.x, latch.x);
            latch.y = fmaf(i, xa[j].y - latch.y, latch.y);
            latch.z = fmaf(i, xa[j].z - latch.z, latch.z);
            latch.w = fmaf(i, xa[j].w - latch.w, latch.w);
            lp[(size_t)(t0 + j) * stride4] = latch;
            d8[j] = dot4(sp4, latch);
            n8[j] = dot4(latch, latch);
        }
        #pragma unroll
        for (int o = 16; o > 0; o >>= 1) {
            #pragma unroll
            for (int j = 0; j < 8; j++) {
                d8[j] += __shfl_xor_sync(0xffffffffu, d8[j], o);
                n8[j] += __shfl_xor_sync(0xffffffffu, n8[j], o);
            }
        }
        if (lane == 0) {
            #pragma unroll
            for (int j = 0; j < 8; j++) {
                int t = t0 + j;
                if (t + 1 < T) { s_wd[t + 1][w] = d8[j]; s_wn[t + 1][w] = n8[j]; }
            }
        }
        // batch B covers t0+8..t0+15 (in xb8); issue loads for t0+16..t0+23
        if (t0 + 16 < T) {
            #pragma unroll
            for (int j = 0; j < 8; j++) xa[j] = xp[(size_t)(t0 + 16 + j) * stride4];
        }
        #pragma unroll
        for (int j = 0; j < 8; j++) {
            float i = s_i[t0 + 8 + j];
            latch.x = fmaf(i, xb8[j].x - latch.x, latch.x);
            latch.y = fmaf(i, xb8[j].y - latch.y, latch.y);
            latch.z = fmaf(i, xb8[j].z - latch.z, latch.z);
            latch.w = fmaf(i, xb8[j].w - latch.w, latch.w);
            lp[(size_t)(t0 + 8 + j) * stride4] = latch;
            d8[j] = dot4(sp4, latch);
            n8[j] = dot4(latch, latch);
        }
        #pragma unroll
        for (int o = 16; o > 0; o >>= 1) {
            #pragma unroll
            for (int j = 0; j < 8; j++) {
                d8[j] += __shfl_xor_sync(0xffffffffu, d8[j], o);
                n8[j] += __shfl_xor_sync(0xffffffffu, n8[j], o);
            }
        }
        if (lane == 0) {
            #pragma unroll
            for (int j = 0; j < 8; j++) {
                int t = t0 + 8 + j;
                if (t + 1 < T) { s_wd[t + 1][w] = d8[j]; s_wn[t + 1][w] = n8[j]; }
            }
        }
    }
    __syncthreads();
    int pbase = (b * 4 + blockIdx.x) * T;
    for (int t = tid; t < T; t += blockDim.x) {
        g_partd[pbase + t] = s_wd[t][0] + s_wd[t][1] + s_wd[t][2] + s_wd[t][3];
        g_partn[pbase + t] = s_wn[t][0] + s_wn[t][1] + s_wn[t][2] + s_wn[t][3];
    }
    if (b == 0 && tid == 0)
        g_partsp[blockIdx.x] = s_sp[0] + s_sp[1] + s_sp[2] + s_sp[3];
}

// ---------------------------------------------------------------------------
// K3b: finalize pop[b,t] = elu(cos) from the 4 per-block partials.
// ---------------------------------------------------------------------------
__global__ void k3b_pops(float* __restrict__ pops, int T) {
    int bt = blockIdx.x * blockDim.x + threadIdx.x;
    int b = bt / T;
    int t = bt - b * T;
    float d = 0.f, n = 0.f;
    #pragma unroll
    for (int blk = 0; blk < 4; blk++) {
        d += g_partd[(b * 4 + blk) * T + t];
        n += g_partn[(b * 4 + blk) * T + t];
    }
    float sp2 = g_partsp[0] + g_partsp[1] + g_partsp[2] + g_partsp[3];
    float nsp = fmaxf(sqrtf(sp2), EPSV);
    float nl = fmaxf(sqrtf(n), EPSV);
    float c = d / (nsp * nl);
    pops[bt] = (c > 0.0f) ? c : expm1f(c);
}

// ---------------------------------------------------------------------------
// Scan step (warp-level): advances ptr one step, writes coef record to buf.
// ---------------------------------------------------------------------------
__device__ __forceinline__ void scan_step(float& ptr, float pop, float sharp, bool fast5,
                                          int lane, bool active, int src_push, int src_pop,
                                          float* __restrict__ buf) {
    const unsigned FULL = 0xffffffffu;
    float push = 1.0f - pop;
    float ptr_push = __shfl_sync(FULL, ptr, src_push);
    float ptr_pop = __shfl_sync(FULL, ptr, src_pop);
    float a = push * (1.0f - ptr_push) + pop * (1.0f - ptr);
    float c = push * ptr_push;
    float e = pop * (ZEROOFF * ptr);
    float mix = push * ptr_push + pop * ptr_pop;
    float pm = fmaxf(mix, 0.0f);
    float pw;
    if (fast5) {
        float p2 = pm * pm;
        pw = p2 * p2 * pm;
    } else {
        pw = powf(pm, sharp);
    }
    float s = active ? pw : 0.0f;
    #pragma unroll
    for (int o = 8; o > 0; o >>= 1) s += __shfl_xor_sync(FULL, s, o);
    float q = __fdividef(pw, s + EPSV);
    if (active) {
        buf[lane] = a;
        buf[12 + lane] = c;
        buf[24 + lane] = e;
        buf[36 + lane] = q;
    }
    if (lane == 0) buf[48] = pop;
    ptr = q;
}

// ---------------------------------------------------------------------------
// K5: fused pointer-scan + stack scan. 5 warps/block: warp 4 produces coef
// records (double-buffered) one step ahead; warps 0-3 consume for 128 float2
// columns with prefetch distance 4 on x. grid (8, B); outer loop unrolled x4.
// ---------------------------------------------------------------------------
__global__ void __launch_bounds__(160)
k5_fused(const float* __restrict__ x, const float* __restrict__ pops,
         const float* __restrict__ sharp_ptr, float* __restrict__ outs,
         float* __restrict__ tops, int T, int V) {
    __shared__ float s_pop[256];
    __shared__ __align__(16) float s_coef[2][CREC];
    int b = blockIdx.y;
    int tid = threadIdx.x;
    int wid = tid >> 5;
    int lane = tid & 31;

    for (int i = tid; i < T; i += blockDim.x) s_pop[i] = pops[b * T + i];
    __syncthreads();

    // scan warp state
    float ptr = (lane == 0) ? 1.0f : 0.0f;
    float sharp = 0.f;
    bool fast5 = false, active = false;
    int src_push = 0, src_pop = 0;
    if (wid == 4) {
        sharp = sharp_ptr[0];
        fast5 = (sharp == 5.0f);
        active = lane < NSTACK;
        src_push = (lane + NSTACK - 1) % NSTACK;
        src_pop = (lane + 1) % NSTACK;
        scan_step(ptr, s_pop[0], sharp, fast5, lane, active, src_push, src_pop, s_coef[0]);
    }

    // stack warp state
    int stride2 = V >> 1;  // 1024 float2 per t
    float stx[NSTACK], sty[NSTACK];
    const float2* xp = 0;
    float2 *op = 0, *tp = 0;
    float2 xbuf[4];
    if (wid < 4) {
        #pragma unroll
        for (int n = 0; n < NSTACK; n++) { stx[n] = ZEROOFF; sty[n] = ZEROOFF; }
        int col = blockIdx.x * 128 + wid * 32 + lane;
        xp = (const float2*)(x + (size_t)b * T * V) + col;
        op = (float2*)(outs + (size_t)b * T * V) + col;
        tp = (float2*)(tops + (size_t)b * T * V) + col;
        #pragma unroll
        for (int j = 0; j < 4; j++) xbuf[j] = xp[(size_t)j * stride2];
    }
    __syncthreads();

    for (int t0 = 0; t0 < T; t0 += 4) {
        #pragma unroll
        for (int j = 0; j < 4; j++) {
            int t = t0 + j;
            if (wid < 4) {
                float2 xv = xbuf[j];
                int tpre = t + 4 < T ? t + 4 : T - 1;     // clamped prefetch
                xbuf[j] = xp[(size_t)tpre * stride2];
                const float4* cf4 = (const float4*)s_coef[t & 1];
                float a[12], c[12], e[12], q[12];
                *(float4*)&a[0] = cf4[0]; *(float4*)&a[4] = cf4[1]; *(float4*)&a[8] = cf4[2];
                *(float4*)&c[0] = cf4[3]; *(float4*)&c[4] = cf4[4]; *(float4*)&c[8] = cf4[5];
                *(float4*)&e[0] = cf4[6]; *(float4*)&e[4] = cf4[7]; *(float4*)&e[8] = cf4[8];
                *(float4*)&q[0] = cf4[9]; *(float4*)&q[4] = cf4[10]; *(float4*)&q[8] = cf4[11];
                float pop = cf4[12].x;
                float topx = 0.f, topy = 0.f;
                #pragma unroll
                for (int n = 0; n < NSTACK; n++) {
                    float wx = fmaf(c[n], xv.x, e[n]);
                    float wy = fmaf(c[n], xv.y, e[n]);
                    stx[n] = fmaf(a[n], stx[n], wx);
                    sty[n] = fmaf(a[n], sty[n], wy);
                    topx = fmaf(stx[n], q[n], topx);
                    topy = fmaf(sty[n], q[n], topy);
                }
                float2 o2; o2.x = pop * topx; o2.y = pop * topy;
                float2 t2; t2.x = topx; t2.y = topy;
                op[(size_t)t * stride2] = o2;
                tp[(size_t)t * stride2] = t2;
            } else {
                if (t + 1 < T)
                    scan_step(ptr, s_pop[t + 1], sharp, fast5, lane, active, src_push, src_pop,
                              s_coef[(t + 1) & 1]);
            }
            __syncthreads();
        }
    }
}

// ---------------------------------------------------------------------------
// Launch (4 kernels). Output layout: [outs BTV][latches BTV][pops BT][tops BTV]
// ---------------------------------------------------------------------------
extern "C" void kernel_launch(void* const* d_in, const int* in_sizes, int n_in,
                              void* d_out, int out_size) {
    const float* x = (const float*)d_in[0];
    const float* sp = (const float*)d_in[1];
    const float* shp = (const float*)d_in[2];
    const float* le = (const float*)d_in[3];
    const float* l0 = (const float*)d_in[4];

    int V = in_sizes[1];
    int B = in_sizes[4] / V;
    int T = in_sizes[0] / in_sizes[4];

    float* out = (float*)d_out;
    size_t btv = (size_t)B * T * V;
    float* outs = out;
    float* latches = out + btv;
    float* pops = out + 2 * btv;
    float* tops = out + 2 * btv + (size_t)B * T;

    k1_interp<<<B * T / 8, 256>>>(x, le, V);
    dim3 g2(4, B);
    k2_latch<<<g2, 128>>>(x, l0, sp, latches, T, V);
    k3b_pops<<<B * T / 256, 256>>>(pops, T);
    dim3 g5(8, B);
    k5_fused<<<g5, 160>>>(x, pops, shp, outs, tops, T, V);
}

// round 7
// speedup vs baseline: 1.8191x; 1.8191x over previous
#include <cuda_runtime.h>
#include <math.h>

#define NSTACK 12
#define ZEROOFF 0.001f
#define EPSV 1e-8f
#define CREC 52      // per-step coef record: a[0:12] c[12:24] e[24:36] q[36:48] pop[48] pad->52
#define CS 32        // chunk size (T steps per chunk)
#define NCH 8        // number of chunks (T/CS)

// Fixed shapes (B=32, T=256, V=2048) for scratch sizing.
__device__ float g_interp[32 * 256];
__device__ float g_partd[32 * 4 * 256];          // per (b, blk, t): partial sp.latch_{t-1}
__device__ float g_partn[32 * 4 * 256];          // per (b, blk, t): partial ||latch_{t-1}||^2
__device__ float g_partsp[4];                    // per blk: partial ||sp||^2
__device__ float g_coef[32 * 256 * CREC];        // per (b,t) coefficient record
__device__ float g_achunk[32 * NCH * NSTACK];    // per (b,ch,n): prod of a over chunk
__device__ float g_W[32 * NCH * NSTACK * 2048];  // chunk affine offset  [b][ch][n][v]
__device__ float g_S[32 * NCH * NSTACK * 2048];  // chunk start states   [b][ch][n][v]

__device__ __forceinline__ float dot4(float4 a, float4 b) {
    return a.x * b.x + a.y * b.y + a.z * b.z + a.w * b.w;
}

// ---------------------------------------------------------------------------
// K1: interp[b,t] = cos(latch_enable, x[b,t]).  One WARP per row, MLP=8.
// ---------------------------------------------------------------------------
__global__ void k1_interp(const float* __restrict__ x, const float* __restrict__ le, int V) {
    int row = blockIdx.x * 8 + (threadIdx.x >> 5);
    int lane = threadIdx.x & 31;
    const float4* xp = (const float4*)(x + (size_t)row * V);
    const float4* le4 = (const float4*)le;
    float d = 0.f, n = 0.f, m = 0.f;
    for (int i0 = lane; i0 < V / 4; i0 += 128) {
        float4 xv[4], l[4];
        #pragma unroll
        for (int j = 0; j < 4; j++) { xv[j] = xp[i0 + 32 * j]; l[j] = le4[i0 + 32 * j]; }
        #pragma unroll
        for (int j = 0; j < 4; j++) {
            d += dot4(l[j], xv[j]);
            n += dot4(xv[j], xv[j]);
            m += dot4(l[j], l[j]);
        }
    }
    #pragma unroll
    for (int o = 16; o > 0; o >>= 1) {
        d += __shfl_xor_sync(0xffffffffu, d, o);
        n += __shfl_xor_sync(0xffffffffu, n, o);
        m += __shfl_xor_sync(0xffffffffu, m, o);
    }
    if (lane == 0) {
        float nle = fmaxf(sqrtf(m), EPSV);
        float nx = fmaxf(sqrtf(n), EPSV);
        g_interp[row] = d / (nle * nx);
    }
}

// ---------------------------------------------------------------------------
// K2: latch scan + fused pop partials (R5 form: 8-step load batches,
// butterflies hoisted out of the recurrence). grid (4, B), block 128.
// ---------------------------------------------------------------------------
__global__ void k2_latch(const float* __restrict__ x, const float* __restrict__ latch0,
                         const float* __restrict__ sp, float* __restrict__ latches,
                         int T, int V) {
    __shared__ float s_i[256];
    __shared__ float s_wd[256][4];
    __shared__ float s_wn[256][4];
    __shared__ float s_sp[4];
    int b = blockIdx.y;
    int tid = threadIdx.x;
    int lane = tid & 31;
    int w = tid >> 5;
    int v4 = blockIdx.x * blockDim.x + tid;
    int stride4 = V >> 2;

    for (int t = tid; t < T; t += blockDim.x) s_i[t] = g_interp[b * T + t];
    __syncthreads();

    float4 sp4 = ((const float4*)sp)[v4];
    float4 latch = ((const float4*)(latch0 + (size_t)b * V))[v4];
    const float4* xp = (const float4*)(x + (size_t)b * T * V) + v4;
    float4* lp = (float4*)(latches + (size_t)b * T * V) + v4;

    {
        float d = dot4(sp4, latch);
        float n = dot4(latch, latch);
        float m = dot4(sp4, sp4);
        #pragma unroll
        for (int o = 16; o > 0; o >>= 1) {
            d += __shfl_xor_sync(0xffffffffu, d, o);
            n += __shfl_xor_sync(0xffffffffu, n, o);
            m += __shfl_xor_sync(0xffffffffu, m, o);
        }
        if (lane == 0) { s_wd[0][w] = d; s_wn[0][w] = n; s_sp[w] = m; }
    }

    for (int t0 = 0; t0 < T; t0 += 8) {
        float4 xs[8];
        #pragma unroll
        for (int j = 0; j < 8; j++) xs[j] = xp[(size_t)(t0 + j) * stride4];
        float d8[8], n8[8];
        #pragma unroll
        for (int j = 0; j < 8; j++) {
            float i = s_i[t0 + j];
            latch.x = fmaf(i, xs[j].x - latch.x, latch.x);
            latch.y = fmaf(i, xs[j].y - latch.y, latch.y);
            latch.z = fmaf(i, xs[j].z - latch.z, latch.z);
            latch.w = fmaf(i, xs[j].w - latch.w, latch.w);
            lp[(size_t)(t0 + j) * stride4] = latch;
            d8[j] = dot4(sp4, latch);
            n8[j] = dot4(latch, latch);
        }
        #pragma unroll
        for (int o = 16; o > 0; o >>= 1) {
            #pragma unroll
            for (int j = 0; j < 8; j++) {
                d8[j] += __shfl_xor_sync(0xffffffffu, d8[j], o);
                n8[j] += __shfl_xor_sync(0xffffffffu, n8[j], o);
            }
        }
        if (lane == 0) {
            #pragma unroll
            for (int j = 0; j < 8; j++) {
                int t = t0 + j;
                if (t + 1 < T) { s_wd[t + 1][w] = d8[j]; s_wn[t + 1][w] = n8[j]; }
            }
        }
    }
    __syncthreads();
    int pbase = (b * 4 + blockIdx.x) * T;
    for (int t = tid; t < T; t += blockDim.x) {
        g_partd[pbase + t] = s_wd[t][0] + s_wd[t][1] + s_wd[t][2] + s_wd[t][3];
        g_partn[pbase + t] = s_wn[t][0] + s_wn[t][1] + s_wn[t][2] + s_wn[t][3];
    }
    if (b == 0 && tid == 0)
        g_partsp[blockIdx.x] = s_sp[0] + s_sp[1] + s_sp[2] + s_sp[3];
}

// ---------------------------------------------------------------------------
// K3b: finalize pop[b,t] = elu(cos) from the 4 per-block partials.
// ---------------------------------------------------------------------------
__global__ void k3b_pops(float* __restrict__ pops, int T) {
    int bt = blockIdx.x * blockDim.x + threadIdx.x;
    int b = bt / T;
    int t = bt - b * T;
    float d = 0.f, n = 0.f;
    #pragma unroll
    for (int blk = 0; blk < 4; blk++) {
        d += g_partd[(b * 4 + blk) * T + t];
        n += g_partn[(b * 4 + blk) * T + t];
    }
    float sp2 = g_partsp[0] + g_partsp[1] + g_partsp[2] + g_partsp[3];
    float nsp = fmaxf(sqrtf(sp2), EPSV);
    float nl = fmaxf(sqrtf(n), EPSV);
    float c = d / (nsp * nl);
    pops[bt] = (c > 0.0f) ? c : expm1f(c);
}

// ---------------------------------------------------------------------------
// K4: pointer scan (serial over T), one warp per batch. Emits per-step coef
// records to g_coef and per-chunk products of a to g_achunk.
// ---------------------------------------------------------------------------
__global__ void k4_ptr(const float* __restrict__ pops, const float* __restrict__ sharp_ptr, int T) {
    const unsigned FULL = 0xffffffffu;
    __shared__ float s_pop[256];
    int b = blockIdx.x;
    int lane = threadIdx.x;
    for (int i = lane; i < T; i += 32) s_pop[i] = pops[b * T + i];
    __syncwarp();
    bool active = lane < NSTACK;
    float sharp = sharp_ptr[0];
    bool fast5 = (sharp == 5.0f);
    float ptr = (lane == 0) ? 1.0f : 0.0f;
    float* cbase = g_coef + (size_t)b * T * CREC;
    int src_push = (lane + NSTACK - 1) % NSTACK;
    int src_pop = (lane + 1) % NSTACK;
    float Aacc = 1.0f;
    for (int t = 0; t < T; t++) {
        float pop = s_pop[t];
        float push = 1.0f - pop;
        float ptr_push = __shfl_sync(FULL, ptr, src_push);
        float ptr_pop = __shfl_sync(FULL, ptr, src_pop);
        float a = push * (1.0f - ptr_push) + pop * (1.0f - ptr);
        float c = push * ptr_push;
        float e = pop * (ZEROOFF * ptr);
        float mix = push * ptr_push + pop * ptr_pop;
        float pm = fmaxf(mix, 0.0f);
        float pw;
        if (fast5) {
            float p2 = pm * pm;
            pw = p2 * p2 * pm;
        } else {
            pw = powf(pm, sharp);
        }
        float s = active ? pw : 0.0f;
        #pragma unroll
        for (int o = 8; o > 0; o >>= 1) s += __shfl_xor_sync(FULL, s, o);
        float q = __fdividef(pw, s + EPSV);
        float* cf = cbase + (size_t)t * CREC;
        if (active) {
            cf[lane] = a;
            cf[12 + lane] = c;
            cf[24 + lane] = e;
            cf[36 + lane] = q;
        }
        if (lane == 0) cf[48] = pop;
        Aacc *= a;
        if ((t & (CS - 1)) == CS - 1) {
            if (active) g_achunk[(b * NCH + (t >> 5)) * NSTACK + lane] = Aacc;
            Aacc = 1.0f;
        }
        ptr = q;
    }
}

// ---------------------------------------------------------------------------
// K6 (pass 1): replay each chunk from st=0 -> result is the chunk's affine
// offset W. grid (vtiles=4, NCH, B), block 256, 1 float2 column per thread.
// ---------------------------------------------------------------------------
__global__ void __launch_bounds__(256)
k6_pass1(const float* __restrict__ x, int T, int V) {
    __shared__ __align__(16) float s_c[CS * CREC];
    int b = blockIdx.z, ch = blockIdx.y;
    int t0 = ch * CS;
    const float4* cg = (const float4*)(g_coef + ((size_t)b * T + t0) * CREC);
    float4* cs4 = (float4*)s_c;
    for (int i = threadIdx.x; i < CS * (CREC / 4); i += blockDim.x) cs4[i] = cg[i];
    __syncthreads();

    int col = blockIdx.x * blockDim.x + threadIdx.x;  // float2 column
    int s2 = V >> 1;
    const float2* xp = (const float2*)(x + (size_t)b * T * V) + (size_t)t0 * s2 + col;

    float stx[NSTACK], sty[NSTACK];
    #pragma unroll
    for (int n = 0; n < NSTACK; n++) { stx[n] = 0.f; sty[n] = 0.f; }

    float2 xbuf[4];
    #pragma unroll
    for (int j = 0; j < 4; j++) xbuf[j] = xp[(size_t)j * s2];

    for (int tt = 0; tt < CS; tt += 4) {
        #pragma unroll
        for (int j = 0; j < 4; j++) {
            int t = tt + j;
            float2 xv = xbuf[j];
            int tpre = (t + 4 < CS) ? t + 4 : CS - 1;
            xbuf[j] = xp[(size_t)tpre * s2];
            const float4* cf4 = (const float4*)(s_c + t * CREC);
            float a[12], c[12], e[12];
            *(float4*)&a[0] = cf4[0]; *(float4*)&a[4] = cf4[1]; *(float4*)&a[8] = cf4[2];
            *(float4*)&c[0] = cf4[3]; *(float4*)&c[4] = cf4[4]; *(float4*)&c[8] = cf4[5];
            *(float4*)&e[0] = cf4[6]; *(float4*)&e[4] = cf4[7]; *(float4*)&e[8] = cf4[8];
            #pragma unroll
            for (int n = 0; n < NSTACK; n++) {
                float wx = fmaf(c[n], xv.x, e[n]);
                float wy = fmaf(c[n], xv.y, e[n]);
                stx[n] = fmaf(a[n], stx[n], wx);
                sty[n] = fmaf(a[n], sty[n], wy);
            }
        }
    }
    float2* Wp = (float2*)g_W + ((size_t)(b * NCH + ch) * NSTACK) * s2 + col;
    #pragma unroll
    for (int n = 0; n < NSTACK; n++) {
        float2 w2; w2.x = stx[n]; w2.y = sty[n];
        Wp[(size_t)n * s2] = w2;
    }
}

// ---------------------------------------------------------------------------
// K7 (combine): S_start[0]=ZEROOFF; S_start[ch+1] = A[ch]*S_start[ch] + W[ch].
// grid (4, B), block 256, 1 float2 column per thread.
// ---------------------------------------------------------------------------
__global__ void __launch_bounds__(256)
k7_combine(int V) {
    __shared__ float sA[NCH][NSTACK];
    int b = blockIdx.y;
    if (threadIdx.x < NCH * NSTACK)
        sA[threadIdx.x / NSTACK][threadIdx.x % NSTACK] = g_achunk[b * NCH * NSTACK + threadIdx.x];
    __syncthreads();
    int col = blockIdx.x * blockDim.x + threadIdx.x;
    int s2 = V >> 1;
    float sx[NSTACK], sy[NSTACK];
    #pragma unroll
    for (int n = 0; n < NSTACK; n++) { sx[n] = ZEROOFF; sy[n] = ZEROOFF; }
    float2* Sp = (float2*)g_S + ((size_t)b * NCH * NSTACK) * s2 + col;
    const float2* Wp = (const float2*)g_W + ((size_t)b * NCH * NSTACK) * s2 + col;
    #pragma unroll
    for (int ch = 0; ch < NCH; ch++) {
        #pragma unroll
        for (int n = 0; n < NSTACK; n++) {
            float2 s2v; s2v.x = sx[n]; s2v.y = sy[n];
            Sp[(size_t)(ch * NSTACK + n) * s2] = s2v;
        }
        if (ch < NCH - 1) {
            float2 w[NSTACK];
            #pragma unroll
            for (int n = 0; n < NSTACK; n++) w[n] = Wp[(size_t)(ch * NSTACK + n) * s2];
            #pragma unroll
            for (int n = 0; n < NSTACK; n++) {
                float A = sA[ch][n];
                sx[n] = fmaf(A, sx[n], w[n].x);
                sy[n] = fmaf(A, sy[n], w[n].y);
            }
        }
    }
}

// ---------------------------------------------------------------------------
// K8 (pass 2): replay each chunk from its start state, writing outs/tops.
// grid (4, NCH, B), block 256.
// ---------------------------------------------------------------------------
__global__ void __launch_bounds__(256)
k8_pass2(const float* __restrict__ x, float* __restrict__ outs,
         float* __restrict__ tops, int T, int V) {
    __shared__ __align__(16) float s_c[CS * CREC];
    int b = blockIdx.z, ch = blockIdx.y;
    int t0 = ch * CS;
    const float4* cg = (const float4*)(g_coef + ((size_t)b * T + t0) * CREC);
    float4* cs4 = (float4*)s_c;
    for (int i = threadIdx.x; i < CS * (CREC / 4); i += blockDim.x) cs4[i] = cg[i];
    __syncthreads();

    int col = blockIdx.x * blockDim.x + threadIdx.x;
    int s2 = V >> 1;
    const float2* xp = (const float2*)(x + (size_t)b * T * V) + (size_t)t0 * s2 + col;
    float2* op = (float2*)(outs + (size_t)b * T * V) + (size_t)t0 * s2 + col;
    float2* tp = (float2*)(tops + (size_t)b * T * V) + (size_t)t0 * s2 + col;

    float stx[NSTACK], sty[NSTACK];
    const float2* Sp = (const float2*)g_S + ((size_t)(b * NCH + ch) * NSTACK) * s2 + col;
    #pragma unroll
    for (int n = 0; n < NSTACK; n++) {
        float2 s2v = Sp[(size_t)n * s2];
        stx[n] = s2v.x; sty[n] = s2v.y;
    }

    float2 xbuf[4];
    #pragma unroll
    for (int j = 0; j < 4; j++) xbuf[j] = xp[(size_t)j * s2];

    for (int tt = 0; tt < CS; tt += 4) {
        #pragma unroll
        for (int j = 0; j < 4; j++) {
            int t = tt + j;
            float2 xv = xbuf[j];
            int tpre = (t + 4 < CS) ? t + 4 : CS - 1;
            xbuf[j] = xp[(size_t)tpre * s2];
            const float4* cf4 = (const float4*)(s_c + t * CREC);
            float a[12], c[12], e[12], q[12];
            *(float4*)&a[0] = cf4[0]; *(float4*)&a[4] = cf4[1]; *(float4*)&a[8] = cf4[2];
            *(float4*)&c[0] = cf4[3]; *(float4*)&c[4] = cf4[4]; *(float4*)&c[8] = cf4[5];
            *(float4*)&e[0] = cf4[6]; *(float4*)&e[4] = cf4[7]; *(float4*)&e[8] = cf4[8];
            *(float4*)&q[0] = cf4[9]; *(float4*)&q[4] = cf4[10]; *(float4*)&q[8] = cf4[11];
            float pop = cf4[12].x;
            float topx = 0.f, topy = 0.f;
            #pragma unroll
            for (int n = 0; n < NSTACK; n++) {
                float wx = fmaf(c[n], xv.x, e[n]);
                float wy = fmaf(c[n], xv.y, e[n]);
                stx[n] = fmaf(a[n], stx[n], wx);
                sty[n] = fmaf(a[n], sty[n], wy);
                topx = fmaf(stx[n], q[n], topx);
                topy = fmaf(sty[n], q[n], topy);
            }
            float2 o2; o2.x = pop * topx; o2.y = pop * topy;
            float2 t2; t2.x = topx; t2.y = topy;
            op[(size_t)t * s2] = o2;
            tp[(size_t)t * s2] = t2;
        }
    }
}

// ---------------------------------------------------------------------------
// Launch (7 kernels). Output layout: [outs BTV][latches BTV][pops BT][tops BTV]
// ---------------------------------------------------------------------------
extern "C" void kernel_launch(void* const* d_in, const int* in_sizes, int n_in,
                              void* d_out, int out_size) {
    const float* x = (const float*)d_in[0];
    const float* sp = (const float*)d_in[1];
    const float* shp = (const float*)d_in[2];
    const float* le = (const float*)d_in[3];
    const float* l0 = (const float*)d_in[4];

    int V = in_sizes[1];
    int B = in_sizes[4] / V;
    int T = in_sizes[0] / in_sizes[4];

    float* out = (float*)d_out;
    size_t btv = (size_t)B * T * V;
    float* outs = out;
    float* latches = out + btv;
    float* pops = out + 2 * btv;
    float* tops = out + 2 * btv + (size_t)B * T;

    k1_interp<<<B * T / 8, 256>>>(x, le, V);
    dim3 g2(4, B);
    k2_latch<<<g2, 128>>>(x, l0, sp, latches, T, V);
    k3b_pops<<<B * T / 256, 256>>>(pops, T);
    k4_ptr<<<B, 32>>>(pops, shp, T);
    dim3 g6(V / 512, NCH, B);
    k6_pass1<<<g6, 256>>>(x, T, V);
    dim3 g7(V / 512, B);
    k7_combine<<<g7, 256>>>(V);
    dim3 g8(V / 512, NCH, B);
    k8_pass2<<<g8, 256>>>(x, outs, tops, T, V);
}